// round 3
// baseline (speedup 1.0000x reference)
#include <cuda_runtime.h>

#define TILE_R 128
#define DIMS   128
#define MSLOTS 64
#define NTHREADS 512

// shared memory layout (floats):
//  xs  [128][132]  x tile, padded
//  ms  [64][128]   memory row-major
//  msT [128][68]   memory transposed (dim-major), padded
//  sims[128][65]   similarity / exp values, padded
//  gw  [128]       gate weights
//  grow[128]       sigmoid gate per row
//  rinv[128]       1/sum(exp) per row
#define XS_PITCH   132
#define MST_PITCH  68
#define SIMS_PITCH 65
#define SMEM_FLOATS (TILE_R*XS_PITCH + MSLOTS*DIMS + DIMS*MST_PITCH + TILE_R*SIMS_PITCH + 3*TILE_R)

typedef unsigned long long ull;

static __device__ __forceinline__ ull pk2(float lo, float hi) {
    ull r; asm("mov.b64 %0, {%1, %2};" : "=l"(r) : "f"(lo), "f"(hi)); return r;
}
static __device__ __forceinline__ ull fma2(ull a, ull b, ull c) {
    ull d; asm("fma.rn.f32x2 %0, %1, %2, %3;" : "=l"(d) : "l"(a), "l"(b), "l"(c)); return d;
}
static __device__ __forceinline__ float2 upk(ull v) {
    float2 f; asm("mov.b64 {%0, %1}, %2;" : "=f"(f.x), "=f"(f.y) : "l"(v)); return f;
}

__global__ __launch_bounds__(NTHREADS, 1)
void gated_memory_kernel(const float* __restrict__ x,
                         const float* __restrict__ mem,
                         const float* __restrict__ gate_w,
                         const float* __restrict__ gate_b,
                         float* __restrict__ out,
                         int n)
{
    extern __shared__ float sm[];
    float* xs   = sm;                            // 128*132
    float* ms   = xs  + TILE_R * XS_PITCH;       // 64*128
    float* msT  = ms  + MSLOTS * DIMS;           // 128*68
    float* sims = msT + DIMS * MST_PITCH;        // 128*65
    float* gw   = sims + TILE_R * SIMS_PITCH;    // 128
    float* grow = gw + DIMS;                     // 128
    float* rinv = grow + TILE_R;                 // 128

    const int tid = threadIdx.x;
    const int tx  = tid & 15;    // 0..15
    const int ty  = tid >> 4;    // 0..31
    const int row0 = blockIdx.x * TILE_R;

    // ---- load memory into ms (row-major) and msT (transposed, padded) ----
    #pragma unroll
    for (int it = 0; it < (MSLOTS * DIMS) / NTHREADS; ++it) {  // 16 iters
        int idx = it * NTHREADS + tid;
        int s = idx >> 7;         // slot
        int d = idx & 127;        // dim
        float v = mem[idx];
        ms[s * DIMS + d] = v;
        msT[d * MST_PITCH + s] = v;
    }
    if (tid < DIMS) gw[tid] = gate_w[tid];

    // ---- load x tile (float4, coalesced), zero-fill OOB rows ----
    {
        const float4* xg = reinterpret_cast<const float4*>(x);
        #pragma unroll
        for (int it = 0; it < (TILE_R * DIMS / 4) / NTHREADS; ++it) {  // 8 iters
            int lin = it * NTHREADS + tid;   // 0..4095
            int r  = lin >> 5;               // row in tile
            int c4 = lin & 31;               // float4 column
            float4 v = make_float4(0.f, 0.f, 0.f, 0.f);
            if (row0 + r < n) v = xg[(size_t)(row0 + r) * 32 + c4];
            *reinterpret_cast<float4*>(&xs[r * XS_PITCH + c4 * 4]) = v;
        }
    }
    __syncthreads();

    // ---- sim GEMM: thread computes rows ty*4..+3, slots tx*4..+3 ----
    const float4* xs4  = reinterpret_cast<const float4*>(xs);   // pitch 33
    const float4* msT4 = reinterpret_cast<const float4*>(msT);  // pitch 17
    {
        ull acc[4][2];
        #pragma unroll
        for (int i = 0; i < 4; ++i) { acc[i][0] = 0ull; acc[i][1] = 0ull; }

        #pragma unroll 4
        for (int k4 = 0; k4 < DIMS / 4; ++k4) {
            float4 mv0 = msT4[(4 * k4 + 0) * (MST_PITCH/4) + tx];
            float4 mv1 = msT4[(4 * k4 + 1) * (MST_PITCH/4) + tx];
            float4 mv2 = msT4[(4 * k4 + 2) * (MST_PITCH/4) + tx];
            float4 mv3 = msT4[(4 * k4 + 3) * (MST_PITCH/4) + tx];
            ull m0a = pk2(mv0.x, mv0.y), m0b = pk2(mv0.z, mv0.w);
            ull m1a = pk2(mv1.x, mv1.y), m1b = pk2(mv1.z, mv1.w);
            ull m2a = pk2(mv2.x, mv2.y), m2b = pk2(mv2.z, mv2.w);
            ull m3a = pk2(mv3.x, mv3.y), m3b = pk2(mv3.z, mv3.w);
            #pragma unroll
            for (int i = 0; i < 4; ++i) {
                float4 xv = xs4[(ty * 4 + i) * (XS_PITCH/4) + k4];
                ull xb;
                xb = pk2(xv.x, xv.x);
                acc[i][0] = fma2(xb, m0a, acc[i][0]); acc[i][1] = fma2(xb, m0b, acc[i][1]);
                xb = pk2(xv.y, xv.y);
                acc[i][0] = fma2(xb, m1a, acc[i][0]); acc[i][1] = fma2(xb, m1b, acc[i][1]);
                xb = pk2(xv.z, xv.z);
                acc[i][0] = fma2(xb, m2a, acc[i][0]); acc[i][1] = fma2(xb, m2b, acc[i][1]);
                xb = pk2(xv.w, xv.w);
                acc[i][0] = fma2(xb, m3a, acc[i][0]); acc[i][1] = fma2(xb, m3b, acc[i][1]);
            }
        }
        // write sim tile to shared
        #pragma unroll
        for (int i = 0; i < 4; ++i) {
            float2 a0 = upk(acc[i][0]);
            float2 a1 = upk(acc[i][1]);
            int r = ty * 4 + i;
            float* sr = &sims[r * SIMS_PITCH + tx * 4];
            sr[0] = a0.x; sr[1] = a0.y; sr[2] = a1.x; sr[3] = a1.y;
        }
    }
    __syncthreads();

    // ---- softmax (warps 0-3) in parallel with gate dot (warps 4-7) ----
    if (tid < TILE_R) {
        // one row per thread; pitch 65 -> conflict-free across lanes
        float* srow = &sims[tid * SIMS_PITCH];
        float mx = srow[0];
        #pragma unroll
        for (int j = 1; j < MSLOTS; ++j) mx = fmaxf(mx, srow[j]);
        float sum = 0.f;
        #pragma unroll
        for (int j = 0; j < MSLOTS; ++j) {
            float e = __expf(srow[j] - mx);
            srow[j] = e;              // store unnormalized exp
            sum += e;
        }
        rinv[tid] = 1.0f / sum;       // fold normalization into epilogue
    } else if (tid < 2 * TILE_R) {
        int r = tid - TILE_R;
        const float4* xr  = reinterpret_cast<const float4*>(&xs[r * XS_PITCH]);
        const float4* gw4 = reinterpret_cast<const float4*>(gw);
        float t = 0.f;
        #pragma unroll
        for (int c = 0; c < DIMS / 4; ++c) {
            float4 a = xr[c], b = gw4[c];
            t += a.x * b.x + a.y * b.y + a.z * b.z + a.w * b.w;
        }
        t += gate_b[0];
        grow[r] = 1.0f / (1.0f + __expf(-t));
    }
    __syncthreads();

    // ---- read GEMM: rows ty*4..+3, dims {4tx..4tx+3} and {64+4tx..+3} ----
    const float4* ms4 = reinterpret_cast<const float4*>(ms);   // pitch 32
    ull racc[4][4];
    #pragma unroll
    for (int i = 0; i < 4; ++i)
        #pragma unroll
        for (int h = 0; h < 4; ++h) racc[i][h] = 0ull;

    #pragma unroll 4
    for (int k = 0; k < MSLOTS; ++k) {
        float4 mlo = ms4[k * 32 + tx];        // dims 4tx..4tx+3
        float4 mhi = ms4[k * 32 + 16 + tx];   // dims 64+4tx..
        ull b0 = pk2(mlo.x, mlo.y), b1 = pk2(mlo.z, mlo.w);
        ull b2 = pk2(mhi.x, mhi.y), b3 = pk2(mhi.z, mhi.w);
        #pragma unroll
        for (int i = 0; i < 4; ++i) {
            float a = sims[(ty * 4 + i) * SIMS_PITCH + k];
            ull ab = pk2(a, a);
            racc[i][0] = fma2(ab, b0, racc[i][0]);
            racc[i][1] = fma2(ab, b1, racc[i][1]);
            racc[i][2] = fma2(ab, b2, racc[i][2]);
            racc[i][3] = fma2(ab, b3, racc[i][3]);
        }
    }

    // ---- epilogue: out = g*read/Z + (1-g)*x ----
    float4* og = reinterpret_cast<float4*>(out);
    #pragma unroll
    for (int i = 0; i < 4; ++i) {
        int r = ty * 4 + i;
        if (row0 + r < n) {
            float g   = grow[r];
            float iz  = rinv[r];
            float gz  = g * iz;
            float omg = 1.0f - g;
            float2 r0 = upk(racc[i][0]), r1 = upk(racc[i][1]);
            float2 r2 = upk(racc[i][2]), r3 = upk(racc[i][3]);
            float4 xlo = xs4[r * (XS_PITCH/4) + tx];
            float4 xhi = xs4[r * (XS_PITCH/4) + 16 + tx];
            float4 o0, o1;
            o0.x = gz * r0.x + omg * xlo.x;
            o0.y = gz * r0.y + omg * xlo.y;
            o0.z = gz * r1.x + omg * xlo.z;
            o0.w = gz * r1.y + omg * xlo.w;
            o1.x = gz * r2.x + omg * xhi.x;
            o1.y = gz * r2.y + omg * xhi.y;
            o1.z = gz * r3.x + omg * xhi.z;
            o1.w = gz * r3.y + omg * xhi.w;
            og[(size_t)(row0 + r) * 32 + tx]      = o0;
            og[(size_t)(row0 + r) * 32 + 16 + tx] = o1;
        }
    }
}

extern "C" void kernel_launch(void* const* d_in, const int* in_sizes, int n_in,
                              void* d_out, int out_size)
{
    const float* x      = (const float*)d_in[0];
    const float* mem    = (const float*)d_in[1];
    const float* gate_w = (const float*)d_in[2];
    const float* gate_b = (const float*)d_in[3];
    float* out = (float*)d_out;

    int n = in_sizes[0] / DIMS;
    int grid = (n + TILE_R - 1) / TILE_R;
    size_t smem = SMEM_FLOATS * sizeof(float);

    cudaFuncSetAttribute(gated_memory_kernel,
                         cudaFuncAttributeMaxDynamicSharedMemorySize, (int)smem);
    gated_memory_kernel<<<grid, NTHREADS, smem>>>(x, mem, gate_w, gate_b, out, n);
}